// round 16
// baseline (speedup 1.0000x reference)
#include <cuda_runtime.h>
#include <cuda_bf16.h>
#include <cstdint>

#define EMB 256
#define H1 1024
#define H2 512
#define NENT 700

// ---------------- scratch (__device__ globals; no allocation) ----------------
__device__ float g_ent[NENT*EMB];
__device__ __nv_bfloat16 g_hA[NENT*H1];
__device__ __nv_bfloat16 g_hB[NENT*H1];
__device__ __nv_bfloat16 g_W2t[H2*H1];   // [n][k]  (W2 transposed, bf16)

// task tables: entity layout [drug 0:200, prot 200:400, dis 400:550, se 550:700]
__constant__ int c_aType[10]  = {0,0,0,0,1,1,1,3,2,2};
__constant__ int c_bType[10]  = {1,0,2,3,2,1,0,0,1,0};
__constant__ int c_base[4]    = {0,200,400,550};
__constant__ int c_cnt[4]     = {200,200,150,150};
__constant__ int c_outOff[10] = {0,40000,80000,110000,140000,170000,210000,250000,280000,310000};

// ---------------- Kernel 1: ent = E @ W_ent, emit drug rows ------------------
__global__ void k_ent(const float* __restrict__ E, const float* __restrict__ W,
                      float* __restrict__ outDrug)
{
    __shared__ float sE[EMB];
    int row = blockIdx.x, tid = threadIdx.x;
    sE[tid] = E[row*EMB + tid];
    __syncthreads();
    float acc = 0.f;
    #pragma unroll 8
    for (int k = 0; k < EMB; ++k) acc = fmaf(sE[k], W[k*EMB + tid], acc);
    g_ent[row*EMB + tid] = acc;
    if (row < 200) outDrug[row*EMB + tid] = acc;
}

// ------------- Kernel 2: hA = bf16(ent@W1a) ; hB = bf16(ent@W1b + b1) --------
__global__ void k_h(const float* __restrict__ W1, const float* __restrict__ b1)
{
    __shared__ float sE[EMB];
    int row = blockIdx.x, which = blockIdx.y, tid = threadIdx.x;
    sE[tid] = g_ent[row*EMB + tid];
    __syncthreads();
    const float* W = W1 + which*EMB*H1;
    float a0=0.f, a1=0.f, a2=0.f, a3=0.f;
    #pragma unroll 4
    for (int k = 0; k < EMB; ++k){
        float e = sE[k];
        const float* w = W + k*H1 + tid;
        a0 = fmaf(e, w[0],   a0);
        a1 = fmaf(e, w[256], a1);
        a2 = fmaf(e, w[512], a2);
        a3 = fmaf(e, w[768], a3);
    }
    if (which){ a0 += b1[tid]; a1 += b1[tid+256]; a2 += b1[tid+512]; a3 += b1[tid+768]; }
    __nv_bfloat16* dst = which ? g_hB : g_hA;
    dst[row*H1 + tid      ] = __float2bfloat16(a0);
    dst[row*H1 + tid + 256] = __float2bfloat16(a1);
    dst[row*H1 + tid + 512] = __float2bfloat16(a2);
    dst[row*H1 + tid + 768] = __float2bfloat16(a3);
}

// ------------- Kernel 2b: W2t[n][k] = bf16(W2[k][n]) -------------------------
__global__ void k_prep(const float* __restrict__ W2)
{
    __shared__ float tile[32][33];
    int k0 = blockIdx.x*32, n0 = blockIdx.y*32;
    int tx = threadIdx.x, ty = threadIdx.y;
    tile[ty][tx] = W2[(k0+ty)*H2 + n0 + tx];
    __syncthreads();
    g_W2t[(uint32_t)(n0+ty)*H1 + k0 + tx] = __float2bfloat16(tile[tx][ty]);
}

// ---------------- mma helpers ------------------------------------------------
__device__ __forceinline__ void cp16cg(void* smem_dst, const void* gmem_src){
    uint32_t s = (uint32_t)__cvta_generic_to_shared(smem_dst);
    asm volatile("cp.async.cg.shared.global [%0], [%1], 16;" :: "r"(s), "l"(gmem_src));
}
__device__ __forceinline__ void ldsm4(uint32_t& r0, uint32_t& r1, uint32_t& r2,
                                      uint32_t& r3, uint32_t addr){
    asm volatile("ldmatrix.sync.aligned.m8n8.x4.shared.b16 {%0,%1,%2,%3}, [%4];"
                 : "=r"(r0), "=r"(r1), "=r"(r2), "=r"(r3) : "r"(addr));
}
__device__ __forceinline__ void mma16816(float* c, const uint32_t* a,
                                         uint32_t b0, uint32_t b1){
    asm volatile(
        "mma.sync.aligned.m16n8k16.row.col.f32.bf16.bf16.f32 "
        "{%0,%1,%2,%3},{%4,%5,%6,%7},{%8,%9},{%0,%1,%2,%3};"
        : "+f"(c[0]), "+f"(c[1]), "+f"(c[2]), "+f"(c[3])
        : "r"(a[0]), "r"(a[1]), "r"(a[2]), "r"(a[3]), "r"(b0), "r"(b1));
}
__device__ __forceinline__ uint32_t haddrelu2(uint32_t a, uint32_t b){
    __nv_bfloat162 s = __hadd2(*(__nv_bfloat162*)&a, *(__nv_bfloat162*)&b);
    __nv_bfloat162 z = __floats2bfloat162_rn(0.f, 0.f);
    s = __hmax2(s, z);
    return *(uint32_t*)&s;
}

// ---------------- Kernel 3: fused pair MLP + softmax (mma.sync) --------------
// CTA: 512 threads, 16 warps (4 wm x 4 wn), warp tile 32x64.
// M=128 pairs (16a x 8b), N=512 in 2 halves of 256, K=1024 in 16 chunks of 64.
// Pipeline: A double-buffer, B/SR ring-4, ONE syncthreads per chunk.
// Warp-parity staggered synth/mma interleave; issue hoisted right after barrier.
#define SA_PITCH 144
#define SB_PITCH 144
#define SR_PITCH 144
#define SA_BUF   (128*SA_PITCH)   // 18432
#define SB_BUF   (256*SB_PITCH)   // 36864
#define SR_BUF   (24*SR_PITCH)    // 3456
#define OFF_SA   0                          // 2 bufs  -> 36864
#define OFF_SB   36864                      // 4 bufs  -> 184320
#define OFF_SR   184320                     // 4 bufs  -> 198144
#define OFF_P0   198144
#define OFF_P1   198656
#define OFF_B2   199168
#define OFF_W3   201216
#define SMEM_REQ 205312

__global__ void __launch_bounds__(512, 1)
k_pairs(const float* __restrict__ b2, const float* __restrict__ W3,
        const float* __restrict__ b3, float* __restrict__ out)
{
    extern __shared__ __align__(16) char sm[];
    const uint32_t smu = (uint32_t)__cvta_generic_to_shared(sm);

    const int task = blockIdx.y;
    const int at = c_aType[task], bt = c_bType[task];
    const int aBase = c_base[at], Na = c_cnt[at];
    const int bBase = c_base[bt], Nb = c_cnt[bt];
    const int tilesA = (Na + 15) >> 4, tilesB = (Nb + 7) >> 3;
    if ((int)blockIdx.x >= tilesA*tilesB) return;
    const int i0 = ((int)blockIdx.x / tilesB) * 16;
    const int j0 = ((int)blockIdx.x % tilesB) * 8;
    const int tid = threadIdx.x;
    const int l   = tid & 31, wid = tid >> 5;
    const int wm  = wid & 3,  wn  = wid >> 2;

    float*  sB2 = (float*)(sm + OFF_B2);
    float2* sW3 = (float2*)(sm + OFF_W3);
    float*  p0s = (float*)(sm + OFF_P0);
    float*  p1s = (float*)(sm + OFF_P1);

    sB2[tid] = b2[tid];
    sW3[tid] = make_float2(W3[2*tid], W3[2*tid+1]);
    if (tid < 128){ p0s[tid] = 0.f; p1s[tid] = 0.f; }
    __syncthreads();

    // lane-constant ldmatrix addresses
    const uint32_t aLane = smu + OFF_SA
        + (uint32_t)(wm*32 + (l&7) + ((l>>3)&1)*8) * SA_PITCH + (uint32_t)((l>>4)*8)*2;
    const uint32_t bLane = smu + OFF_SB
        + (uint32_t)(wn*64 + (l&7) + (l>>4)*8) * SB_PITCH + (uint32_t)(((l>>3)&1)*8)*2;

    // synth mapping: 4 threads per A row, 16 bf16 cols (32B) each
    const int sm_m  = tid >> 2;
    const int sm_sg = tid & 3;
    const int sr_rowA = sm_m >> 3;          // 0..15
    const int sr_rowB = 16 + (sm_m & 7);    // 16..23

    float acc[2][8][4];

    for (int nh = 0; nh < 2; ++nh){
        #pragma unroll
        for (int mt = 0; mt < 2; ++mt)
            #pragma unroll
            for (int nt = 0; nt < 8; ++nt)
                #pragma unroll
                for (int r = 0; r < 4; ++r) acc[mt][nt][r] = 0.f;

        // ---- cp.async issuer: B chunk (ring) + 24 distinct bf16 rows (ring) ----
        auto issue = [&](int c, int ring){
            #pragma unroll
            for (int i = 0; i < 4; ++i){
                int idx = tid + i*512;
                int row = idx >> 3, seg = idx & 7;
                cp16cg(sm + OFF_SB + ring*SB_BUF + row*SB_PITCH + seg*16,
                       g_W2t + (uint32_t)(nh*256 + row)*H1 + c*64 + seg*8);
            }
            if (tid < 192){
                int row = tid >> 3, seg = tid & 7;
                const __nv_bfloat16* src;
                if (row < 16){
                    int r = aBase + min(i0 + row, Na - 1);
                    src = g_hA + (uint32_t)r*H1;
                } else {
                    int r = bBase + min(j0 + row - 16, Nb - 1);
                    src = g_hB + (uint32_t)r*H1;
                }
                cp16cg(sm + OFF_SR + ring*SR_BUF + row*SR_PITCH + seg*16,
                       src + c*64 + seg*8);
            }
            asm volatile("cp.async.commit_group;");
        };

        // ---- one kt-step of the mma over a staged chunk (A parity, B ring) ----
        auto domma_kt = [&](int cc, int kt){
            const uint32_t aAdr = aLane + (cc & 1)*SA_BUF;
            const uint32_t bAdr = bLane + (cc & 3)*SB_BUF;
            uint32_t a0[4], a1[4];
            ldsm4(a0[0], a0[1], a0[2], a0[3], aAdr + kt*32);
            ldsm4(a1[0], a1[1], a1[2], a1[3], aAdr + kt*32 + 16*SA_PITCH);
            #pragma unroll
            for (int np = 0; np < 4; ++np){
                uint32_t b0, b1v, b2v, b3v;
                ldsm4(b0, b1v, b2v, b3v, bAdr + np*16*SB_PITCH + kt*32);
                mma16816(acc[0][np*2],   a0, b0,  b1v);
                mma16816(acc[0][np*2+1], a0, b2v, b3v);
                mma16816(acc[1][np*2],   a1, b0,  b1v);
                mma16816(acc[1][np*2+1], a1, b2v, b3v);
            }
        };

        // ---- half of the A-synthesis for chunk c (q = 0 or 1) ----
        auto synth_q = [&](int c, int q){
            const char* rbuf = sm + OFF_SR + (c & 3)*SR_BUF;
            const uint4* ra = (const uint4*)(rbuf + sr_rowA*SR_PITCH + sm_sg*32);
            const uint4* rb = (const uint4*)(rbuf + sr_rowB*SR_PITCH + sm_sg*32);
            uint4* dst = (uint4*)(sm + OFF_SA + (c & 1)*SA_BUF
                                  + sm_m*SA_PITCH + sm_sg*32);
            uint4 x = ra[q], y = rb[q];
            uint4 w;
            w.x = haddrelu2(x.x, y.x);
            w.y = haddrelu2(x.y, y.y);
            w.z = haddrelu2(x.z, y.z);
            w.w = haddrelu2(x.w, y.w);
            dst[q] = w;
        };

        issue(0, 0);
        issue(1, 1);

        for (int c = 0; c < 16; ++c){
            if (c == 15) asm volatile("cp.async.wait_group 0;" ::: "memory");
            else         asm volatile("cp.async.wait_group 1;" ::: "memory");
            __syncthreads();

            // prefetch for c+2 as early as possible: buffer (c+2)&3 was last
            // read by mma(c-2) inside body(c-1), which the barrier just closed.
            if (c > 0 && c + 2 < 16) issue(c + 2, (c + 2) & 3);

            if (c > 0){
                if (wid & 1){
                    // odd warps: mma-first
                    domma_kt(c - 1, 0);
                    synth_q(c, 0);
                    domma_kt(c - 1, 1);
                    synth_q(c, 1);
                    domma_kt(c - 1, 2);
                    domma_kt(c - 1, 3);
                } else {
                    // even warps: synth-first
                    synth_q(c, 0);
                    domma_kt(c - 1, 0);
                    synth_q(c, 1);
                    domma_kt(c - 1, 1);
                    domma_kt(c - 1, 2);
                    domma_kt(c - 1, 3);
                }
            } else {
                synth_q(0, 0);
                synth_q(0, 1);
                issue(2, 2);
            }
        }
        __syncthreads();   // synth(15) visible
        domma_kt(15, 0); domma_kt(15, 1); domma_kt(15, 2); domma_kt(15, 3);

        // fold this N-half into (p0,p1): relu(acc+b2) dot W3
        {
            const int quad = l >> 2, tq = l & 3;
            float pa0[2][2] = {{0.f,0.f},{0.f,0.f}};
            float pa1[2][2] = {{0.f,0.f},{0.f,0.f}};
            #pragma unroll
            for (int mt = 0; mt < 2; ++mt)
                #pragma unroll
                for (int nt = 0; nt < 8; ++nt)
                    #pragma unroll
                    for (int r = 0; r < 4; ++r){
                        int ng = nh*256 + wn*64 + nt*8 + tq*2 + (r & 1);
                        float v = fmaxf(acc[mt][nt][r] + sB2[ng], 0.f);
                        float2 w = sW3[ng];
                        pa0[mt][r>>1] = fmaf(v, w.x, pa0[mt][r>>1]);
                        pa1[mt][r>>1] = fmaf(v, w.y, pa1[mt][r>>1]);
                    }
            #pragma unroll
            for (int mt = 0; mt < 2; ++mt)
                #pragma unroll
                for (int rh = 0; rh < 2; ++rh){
                    float q0 = pa0[mt][rh], q1 = pa1[mt][rh];
                    q0 += __shfl_xor_sync(0xffffffffu, q0, 1);
                    q0 += __shfl_xor_sync(0xffffffffu, q0, 2);
                    q1 += __shfl_xor_sync(0xffffffffu, q1, 1);
                    q1 += __shfl_xor_sync(0xffffffffu, q1, 2);
                    if (tq == 0){
                        int m = wm*32 + mt*16 + quad + rh*8;
                        atomicAdd(&p0s[m], q0);
                        atomicAdd(&p1s[m], q1);
                    }
                }
        }
        __syncthreads();
    }

    // softmax + write
    if (tid < 128){
        int ia = i0 + (tid >> 3), jb = j0 + (tid & 7);
        if (ia < Na && jb < Nb){
            float l0 = p0s[tid] + b3[0], l1 = p1s[tid] + b3[1];
            float mx = fmaxf(l0, l1);
            float e0 = expf(l0 - mx), e1 = expf(l1 - mx);
            float inv = 1.f / (e0 + e1);
            int idx = (c_outOff[task] + ia*Nb + jb) * 2;
            out[idx]   = e0 * inv;
            out[idx+1] = e1 * inv;
        }
    }
}

// -----------------------------------------------------------------------------
extern "C" void kernel_launch(void* const* d_in, const int* in_sizes, int n_in,
                              void* d_out, int out_size)
{
    // 0 type_mask, 1 entity_embedding, 2 relation_embedding, 3 W_ent, 4 W_rel,
    // 5 W1, 6 b1, 7 W2, 8 b2, 9 W3, 10 b3
    const float* E    = (const float*)d_in[1];
    const float* Went = (const float*)d_in[3];
    const float* W1   = (const float*)d_in[5];
    const float* b1   = (const float*)d_in[6];
    const float* W2   = (const float*)d_in[7];
    const float* b2   = (const float*)d_in[8];
    const float* W3   = (const float*)d_in[9];
    const float* b3   = (const float*)d_in[10];
    float* out = (float*)d_out;

    k_ent<<<700, 256>>>(E, Went, out + 680000);
    k_h<<<dim3(700, 2), 256>>>(W1, b1);
    k_prep<<<dim3(32, 16), dim3(32, 32)>>>(W2);

    cudaFuncSetAttribute(k_pairs, cudaFuncAttributeMaxDynamicSharedMemorySize, SMEM_REQ);
    k_pairs<<<dim3(325, 10), 512, SMEM_REQ>>>(b2, W3, b3, out);
}

// round 17
// speedup vs baseline: 1.1828x; 1.1828x over previous
#include <cuda_runtime.h>
#include <cuda_bf16.h>
#include <cstdint>

#define EMB 256
#define H1 1024
#define H2 512
#define NENT 700

// ---------------- scratch (__device__ globals; no allocation) ----------------
__device__ float g_ent[NENT*EMB];
__device__ __nv_bfloat16 g_hA[NENT*H1];
__device__ __nv_bfloat16 g_hB[NENT*H1];
__device__ __nv_bfloat16 g_W2t[H2*H1];   // [n][k]  (W2 transposed, bf16)

// task tables: entity layout [drug 0:200, prot 200:400, dis 400:550, se 550:700]
__constant__ int c_aType[10]  = {0,0,0,0,1,1,1,3,2,2};
__constant__ int c_bType[10]  = {1,0,2,3,2,1,0,0,1,0};
__constant__ int c_base[4]    = {0,200,400,550};
__constant__ int c_cnt[4]     = {200,200,150,150};
__constant__ int c_outOff[10] = {0,40000,80000,110000,140000,170000,210000,250000,280000,310000};

// ------- Kernel 1: ent = E @ W_ent (8 rows/block, W streamed once/block) -----
__global__ void k_ent(const float* __restrict__ E, const float* __restrict__ W,
                      float* __restrict__ outDrug)
{
    __shared__ float sE[8*EMB];
    const int r0 = blockIdx.x * 8, tid = threadIdx.x;
    #pragma unroll
    for (int i = 0; i < 2; ++i){
        int idx = tid + i*256;              // 512 float4 total
        int row = idx >> 6, c4 = idx & 63;
        ((float4*)sE)[idx] =
            ((const float4*)(E + (uint32_t)min(r0 + row, NENT-1)*EMB))[c4];
    }
    __syncthreads();
    float acc[8] = {0,0,0,0,0,0,0,0};
    #pragma unroll 4
    for (int k = 0; k < EMB; ++k){
        float w = W[k*EMB + tid];
        #pragma unroll
        for (int r = 0; r < 8; ++r) acc[r] = fmaf(sE[r*EMB + k], w, acc[r]);
    }
    #pragma unroll
    for (int r = 0; r < 8; ++r){
        int row = r0 + r;
        if (row < NENT){
            g_ent[(uint32_t)row*EMB + tid] = acc[r];
            if (row < 200) outDrug[(uint32_t)row*EMB + tid] = acc[r];
        }
    }
}

// ------- Kernel 2: hA/hB (16 rows/block, 256-col slab, W1 streamed once) -----
// grid: (ceil(700/16)=44, 4 col-slabs, 2 which)
__global__ void k_h(const float* __restrict__ W1, const float* __restrict__ b1)
{
    __shared__ float sE[16*EMB];
    const int r0 = blockIdx.x * 16;
    const int cb = blockIdx.y * 256;
    const int which = blockIdx.z;
    const int tid = threadIdx.x;
    #pragma unroll
    for (int i = 0; i < 4; ++i){
        int idx = tid + i*256;              // 1024 float4 total
        int row = idx >> 6, c4 = idx & 63;
        ((float4*)sE)[idx] =
            ((const float4*)(g_ent + (uint32_t)min(r0 + row, NENT-1)*EMB))[c4];
    }
    __syncthreads();
    const float* W = W1 + (uint32_t)which*EMB*H1 + cb + tid;
    float acc[16];
    #pragma unroll
    for (int r = 0; r < 16; ++r) acc[r] = 0.f;
    #pragma unroll 4
    for (int k = 0; k < EMB; ++k){
        float w = W[k*H1];
        #pragma unroll
        for (int r = 0; r < 16; ++r) acc[r] = fmaf(sE[r*EMB + k], w, acc[r]);
    }
    float bias = which ? b1[cb + tid] : 0.f;
    __nv_bfloat16* dst = which ? g_hB : g_hA;
    #pragma unroll
    for (int r = 0; r < 16; ++r){
        int row = r0 + r;
        if (row < NENT)
            dst[(uint32_t)row*H1 + cb + tid] = __float2bfloat16(acc[r] + bias);
    }
}

// ------------- Kernel 2b: W2t[n][k] = bf16(W2[k][n]) -------------------------
__global__ void k_prep(const float* __restrict__ W2)
{
    __shared__ float tile[32][33];
    int k0 = blockIdx.x*32, n0 = blockIdx.y*32;
    int tx = threadIdx.x, ty = threadIdx.y;
    tile[ty][tx] = W2[(k0+ty)*H2 + n0 + tx];
    __syncthreads();
    g_W2t[(uint32_t)(n0+ty)*H1 + k0 + tx] = __float2bfloat16(tile[tx][ty]);
}

// ---------------- mma helpers ------------------------------------------------
__device__ __forceinline__ void cp16cg(void* smem_dst, const void* gmem_src){
    uint32_t s = (uint32_t)__cvta_generic_to_shared(smem_dst);
    asm volatile("cp.async.cg.shared.global [%0], [%1], 16;" :: "r"(s), "l"(gmem_src));
}
__device__ __forceinline__ void ldsm4(uint32_t& r0, uint32_t& r1, uint32_t& r2,
                                      uint32_t& r3, uint32_t addr){
    asm volatile("ldmatrix.sync.aligned.m8n8.x4.shared.b16 {%0,%1,%2,%3}, [%4];"
                 : "=r"(r0), "=r"(r1), "=r"(r2), "=r"(r3) : "r"(addr));
}
__device__ __forceinline__ void mma16816(float* c, const uint32_t* a,
                                         uint32_t b0, uint32_t b1){
    asm volatile(
        "mma.sync.aligned.m16n8k16.row.col.f32.bf16.bf16.f32 "
        "{%0,%1,%2,%3},{%4,%5,%6,%7},{%8,%9},{%0,%1,%2,%3};"
        : "+f"(c[0]), "+f"(c[1]), "+f"(c[2]), "+f"(c[3])
        : "r"(a[0]), "r"(a[1]), "r"(a[2]), "r"(a[3]), "r"(b0), "r"(b1));
}
__device__ __forceinline__ uint32_t haddrelu2(uint32_t a, uint32_t b){
    __nv_bfloat162 s = __hadd2(*(__nv_bfloat162*)&a, *(__nv_bfloat162*)&b);
    __nv_bfloat162 z = __floats2bfloat162_rn(0.f, 0.f);
    s = __hmax2(s, z);
    return *(uint32_t*)&s;
}

// ---------------- Kernel 3: fused pair MLP + softmax (mma.sync) --------------
// Exact R10 configuration (best measured): 512 threads, 16 warps (4x4),
// warp tile 32x64; M=128, N=512 in 2 halves, K=1024 in 16 chunks of 64.
// A double-buffer, B/SR ring-4, one syncthreads per chunk, per-kt interleave.
#define SA_PITCH 144
#define SB_PITCH 144
#define SR_PITCH 144
#define SA_BUF   (128*SA_PITCH)   // 18432
#define SB_BUF   (256*SB_PITCH)   // 36864
#define SR_BUF   (24*SR_PITCH)    // 3456
#define OFF_SA   0                          // 2 bufs  -> 36864
#define OFF_SB   36864                      // 4 bufs  -> 184320
#define OFF_SR   184320                     // 4 bufs  -> 198144
#define OFF_P0   198144
#define OFF_P1   198656
#define OFF_B2   199168
#define OFF_W3   201216
#define SMEM_REQ 205312

__global__ void __launch_bounds__(512, 1)
k_pairs(const float* __restrict__ b2, const float* __restrict__ W3,
        const float* __restrict__ b3, float* __restrict__ out)
{
    extern __shared__ __align__(16) char sm[];
    const uint32_t smu = (uint32_t)__cvta_generic_to_shared(sm);

    const int task = blockIdx.y;
    const int at = c_aType[task], bt = c_bType[task];
    const int aBase = c_base[at], Na = c_cnt[at];
    const int bBase = c_base[bt], Nb = c_cnt[bt];
    const int tilesA = (Na + 15) >> 4, tilesB = (Nb + 7) >> 3;
    if ((int)blockIdx.x >= tilesA*tilesB) return;
    const int i0 = ((int)blockIdx.x / tilesB) * 16;
    const int j0 = ((int)blockIdx.x % tilesB) * 8;
    const int tid = threadIdx.x;
    const int l   = tid & 31, wid = tid >> 5;
    const int wm  = wid & 3,  wn  = wid >> 2;

    float*  sB2 = (float*)(sm + OFF_B2);
    float2* sW3 = (float2*)(sm + OFF_W3);
    float*  p0s = (float*)(sm + OFF_P0);
    float*  p1s = (float*)(sm + OFF_P1);

    sB2[tid] = b2[tid];
    sW3[tid] = make_float2(W3[2*tid], W3[2*tid+1]);
    if (tid < 128){ p0s[tid] = 0.f; p1s[tid] = 0.f; }
    __syncthreads();

    // lane-constant ldmatrix addresses
    const uint32_t aLane = smu + OFF_SA
        + (uint32_t)(wm*32 + (l&7) + ((l>>3)&1)*8) * SA_PITCH + (uint32_t)((l>>4)*8)*2;
    const uint32_t bLane = smu + OFF_SB
        + (uint32_t)(wn*64 + (l&7) + (l>>4)*8) * SB_PITCH + (uint32_t)(((l>>3)&1)*8)*2;

    // synth mapping: 4 threads per A row, 16 bf16 cols (32B) each
    const int sm_m  = tid >> 2;
    const int sm_sg = tid & 3;
    const int sr_rowA = sm_m >> 3;          // 0..15
    const int sr_rowB = 16 + (sm_m & 7);    // 16..23

    float acc[2][8][4];

    for (int nh = 0; nh < 2; ++nh){
        #pragma unroll
        for (int mt = 0; mt < 2; ++mt)
            #pragma unroll
            for (int nt = 0; nt < 8; ++nt)
                #pragma unroll
                for (int r = 0; r < 4; ++r) acc[mt][nt][r] = 0.f;

        // ---- cp.async issuer: B chunk (ring) + 24 distinct bf16 rows (ring) ----
        auto issue = [&](int c, int ring){
            #pragma unroll
            for (int i = 0; i < 4; ++i){
                int idx = tid + i*512;
                int row = idx >> 3, seg = idx & 7;
                cp16cg(sm + OFF_SB + ring*SB_BUF + row*SB_PITCH + seg*16,
                       g_W2t + (uint32_t)(nh*256 + row)*H1 + c*64 + seg*8);
            }
            if (tid < 192){
                int row = tid >> 3, seg = tid & 7;
                const __nv_bfloat16* src;
                if (row < 16){
                    int r = aBase + min(i0 + row, Na - 1);
                    src = g_hA + (uint32_t)r*H1;
                } else {
                    int r = bBase + min(j0 + row - 16, Nb - 1);
                    src = g_hB + (uint32_t)r*H1;
                }
                cp16cg(sm + OFF_SR + ring*SR_BUF + row*SR_PITCH + seg*16,
                       src + c*64 + seg*8);
            }
            asm volatile("cp.async.commit_group;");
        };

        // ---- one kt-step of the mma over a staged chunk (A parity, B ring) ----
        auto domma_kt = [&](int cc, int kt){
            const uint32_t aAdr = aLane + (cc & 1)*SA_BUF;
            const uint32_t bAdr = bLane + (cc & 3)*SB_BUF;
            uint32_t a0[4], a1[4];
            ldsm4(a0[0], a0[1], a0[2], a0[3], aAdr + kt*32);
            ldsm4(a1[0], a1[1], a1[2], a1[3], aAdr + kt*32 + 16*SA_PITCH);
            #pragma unroll
            for (int np = 0; np < 4; ++np){
                uint32_t b0, b1v, b2v, b3v;
                ldsm4(b0, b1v, b2v, b3v, bAdr + np*16*SB_PITCH + kt*32);
                mma16816(acc[0][np*2],   a0, b0,  b1v);
                mma16816(acc[0][np*2+1], a0, b2v, b3v);
                mma16816(acc[1][np*2],   a1, b0,  b1v);
                mma16816(acc[1][np*2+1], a1, b2v, b3v);
            }
        };

        // ---- half of the A-synthesis for chunk c (q = 0 or 1) ----
        auto synth_q = [&](int c, int q){
            const char* rbuf = sm + OFF_SR + (c & 3)*SR_BUF;
            const uint4* ra = (const uint4*)(rbuf + sr_rowA*SR_PITCH + sm_sg*32);
            const uint4* rb = (const uint4*)(rbuf + sr_rowB*SR_PITCH + sm_sg*32);
            uint4* dst = (uint4*)(sm + OFF_SA + (c & 1)*SA_BUF
                                  + sm_m*SA_PITCH + sm_sg*32);
            uint4 x = ra[q], y = rb[q];
            uint4 w;
            w.x = haddrelu2(x.x, y.x);
            w.y = haddrelu2(x.y, y.y);
            w.z = haddrelu2(x.z, y.z);
            w.w = haddrelu2(x.w, y.w);
            dst[q] = w;
        };

        issue(0, 0);
        issue(1, 1);

        for (int c = 0; c < 16; ++c){
            if (c == 15) asm volatile("cp.async.wait_group 0;" ::: "memory");
            else         asm volatile("cp.async.wait_group 1;" ::: "memory");
            __syncthreads();

            if (c > 0){
                domma_kt(c - 1, 0);
                synth_q(c, 0);
                domma_kt(c - 1, 1);
                synth_q(c, 1);
                domma_kt(c - 1, 2);
                if (c + 2 < 16) issue(c + 2, (c + 2) & 3);
                domma_kt(c - 1, 3);
            } else {
                synth_q(0, 0);
                synth_q(0, 1);
                issue(2, 2);
            }
        }
        __syncthreads();   // synth(15) visible
        domma_kt(15, 0); domma_kt(15, 1); domma_kt(15, 2); domma_kt(15, 3);

        // fold this N-half into (p0,p1): relu(acc+b2) dot W3
        {
            const int quad = l >> 2, tq = l & 3;
            float pa0[2][2] = {{0.f,0.f},{0.f,0.f}};
            float pa1[2][2] = {{0.f,0.f},{0.f,0.f}};
            #pragma unroll
            for (int mt = 0; mt < 2; ++mt)
                #pragma unroll
                for (int nt = 0; nt < 8; ++nt)
                    #pragma unroll
                    for (int r = 0; r < 4; ++r){
                        int ng = nh*256 + wn*64 + nt*8 + tq*2 + (r & 1);
                        float v = fmaxf(acc[mt][nt][r] + sB2[ng], 0.f);
                        float2 w = sW3[ng];
                        pa0[mt][r>>1] = fmaf(v, w.x, pa0[mt][r>>1]);
                        pa1[mt][r>>1] = fmaf(v, w.y, pa1[mt][r>>1]);
                    }
            #pragma unroll
            for (int mt = 0; mt < 2; ++mt)
                #pragma unroll
                for (int rh = 0; rh < 2; ++rh){
                    float q0 = pa0[mt][rh], q1 = pa1[mt][rh];
                    q0 += __shfl_xor_sync(0xffffffffu, q0, 1);
                    q0 += __shfl_xor_sync(0xffffffffu, q0, 2);
                    q1 += __shfl_xor_sync(0xffffffffu, q1, 1);
                    q1 += __shfl_xor_sync(0xffffffffu, q1, 2);
                    if (tq == 0){
                        int m = wm*32 + mt*16 + quad + rh*8;
                        atomicAdd(&p0s[m], q0);
                        atomicAdd(&p1s[m], q1);
                    }
                }
        }
        __syncthreads();
    }

    // softmax + write
    if (tid < 128){
        int ia = i0 + (tid >> 3), jb = j0 + (tid & 7);
        if (ia < Na && jb < Nb){
            float l0 = p0s[tid] + b3[0], l1 = p1s[tid] + b3[1];
            float mx = fmaxf(l0, l1);
            float e0 = expf(l0 - mx), e1 = expf(l1 - mx);
            float inv = 1.f / (e0 + e1);
            int idx = (c_outOff[task] + ia*Nb + jb) * 2;
            out[idx]   = e0 * inv;
            out[idx+1] = e1 * inv;
        }
    }
}

// -----------------------------------------------------------------------------
extern "C" void kernel_launch(void* const* d_in, const int* in_sizes, int n_in,
                              void* d_out, int out_size)
{
    // 0 type_mask, 1 entity_embedding, 2 relation_embedding, 3 W_ent, 4 W_rel,
    // 5 W1, 6 b1, 7 W2, 8 b2, 9 W3, 10 b3
    const float* E    = (const float*)d_in[1];
    const float* Went = (const float*)d_in[3];
    const float* W1   = (const float*)d_in[5];
    const float* b1   = (const float*)d_in[6];
    const float* W2   = (const float*)d_in[7];
    const float* b2   = (const float*)d_in[8];
    const float* W3   = (const float*)d_in[9];
    const float* b3   = (const float*)d_in[10];
    float* out = (float*)d_out;

    k_ent<<<(NENT + 7)/8, 256>>>(E, Went, out + 680000);
    k_h<<<dim3((NENT + 15)/16, 4, 2), 256>>>(W1, b1);
    k_prep<<<dim3(32, 16), dim3(32, 32)>>>(W2);

    cudaFuncSetAttribute(k_pairs, cudaFuncAttributeMaxDynamicSharedMemorySize, SMEM_REQ);
    k_pairs<<<dim3(325, 10), 512, SMEM_REQ>>>(b2, W3, b3, out);
}